// round 6
// baseline (speedup 1.0000x reference)
#include <cuda_runtime.h>

#define FULLMASK 0xFFFFFFFFu

#define HID   64
#define G4    256
#define RS    8
#define KIH   24
#define WIDTH 24
#define L0R   8
#define R0R   24
#define OW    16
#define GB    16         // batches per 4-warp group
#define NGRP  2
#define NTHR  256
#define CTAB  32

#define KQ_IN  6
#define KQ_HID 16
#define KQTOT  22

// smem float offsets
#define OFF_W    0
#define W_FLOATS (4*KQTOT*2*32*4)            // 22528
#define OFF_BIAS (OFF_W + W_FLOATS)          // 22528
#define OFF_WL   (OFF_BIAS + G4)             // 22784
#define OFF_BL   (OFF_WL + 3*HID)            // 22976
#define OFF_HX   (OFF_BL + 4)                // 22980 (16B aligned: 22980*4%16==0)
#define HX_FLOATS (NGRP*GB*HID)              // 2048
#define OFF_XCH  (OFF_HX + HX_FLOATS)        // 25028
#define XCH_FLOATS (NGRP*4*GB*32*2)          // 8192
#define OFF_RBQ  (OFF_XCH + XCH_FLOATS)      // 33220
#define RBQ_FLOATS (NGRP*GB*3*WIDTH*4)       // 9216
#define SMEM_FLOATS (OFF_RBQ + RBQ_FLOATS)   // 42436 -> ~166 KB

typedef unsigned long long u64;

union F4U { float4 f4; struct { u64 lo, hi; } u; };

static __device__ __forceinline__ u64 pack2(float a, float b){
  u64 r; asm("mov.b64 %0, {%1, %2};" : "=l"(r) : "f"(a), "f"(b)); return r;
}
static __device__ __forceinline__ void unpack2(u64 v, float& a, float& b){
  asm("mov.b64 {%0, %1}, %2;" : "=f"(a), "=f"(b) : "l"(v));
}
static __device__ __forceinline__ u64 ffma2(u64 a, u64 b, u64 c){
  u64 d; asm("fma.rn.f32x2 %0, %1, %2, %3;" : "=l"(d) : "l"(a), "l"(b), "l"(c));
  return d;
}
static __device__ __forceinline__ float tanha(float x){
  float y; asm("tanh.approx.f32 %0, %1;" : "=f"(y) : "f"(x)); return y;
}
static __device__ __forceinline__ float sigf(float x){
  return fmaf(tanha(0.5f*x), 0.5f, 0.5f);
}

#define GBAR() asm volatile("bar.sync %0, 128;" :: "r"(grp + 1) : "memory")

__global__ void __launch_bounds__(NTHR, 1)
pixelrnn_kernel(const float* __restrict__ x,
                const float* __restrict__ W_ih,
                const float* __restrict__ W_hh,
                const float* __restrict__ b_ih,
                const float* __restrict__ b_hh,
                const float* __restrict__ Wl,
                const float* __restrict__ bl,
                float* __restrict__ out)
{
  extern __shared__ float sm[];
  const int tid  = threadIdx.x;
  const int warp = tid >> 5, lane = tid & 31;
  const int grp  = warp >> 2;          // 2 groups of 4 warps, 16 batches each
  const int q    = warp & 3;           // gate type: 0=i 1=f 2=g 3=o

  // ---- stage weights (shared across groups) ----
  // float4 Wq[((qt*22 + kq)*2 + p)*32 + ln] =
  //   ( w(k,g0), w(k+1,g0), w(k,g1), w(k+1,g1) ),  g0 = 64*qt + ln, g1 = g0+32
  //   kq<6:  k = (kq>>1)*8 + (kq&1)*4 + 2p   (input)
  //   kq>=6: k = 4*(kq-6) + 2p               (hidden)
  {
    float4* Wq = (float4*)(sm + OFF_W);
    for (int i = tid; i < 4*KQTOT*2*32; i += NTHR){
      int ln = i & 31;
      int p  = (i >> 5) & 1;
      int kq = (i >> 6) % KQTOT;
      int qt = (i >> 6) / KQTOT;
      int g0 = 64*qt + ln, g1 = g0 + 32;
      float4 v;
      if (kq < KQ_IN){
        int kk = (kq>>1)*8 + (kq&1)*4 + 2*p;
        v = make_float4(W_ih[g0*KIH + kk], W_ih[g0*KIH + kk + 1],
                        W_ih[g1*KIH + kk], W_ih[g1*KIH + kk + 1]);
      } else {
        int kk = 4*(kq - KQ_IN) + 2*p;
        v = make_float4(W_hh[g0*HID + kk], W_hh[g0*HID + kk + 1],
                        W_hh[g1*HID + kk], W_hh[g1*HID + kk + 1]);
      }
      Wq[i] = v;
    }
  }
  for (int i = tid; i < G4; i += NTHR) sm[OFF_BIAS + i] = b_ih[i] + b_hh[i];
  for (int i = tid; i < 3*HID; i += NTHR) sm[OFF_WL + i] = Wl[i];
  if (tid < 3) sm[OFF_BL + tid] = bl[tid];
  for (int i = tid; i < HX_FLOATS; i += NTHR) sm[OFF_HX + i] = 0.f;
  __syncthreads();

  const int bgrp = blockIdx.x * CTAB + grp * GB;
  float*  hxs = sm + OFF_HX + grp * (GB*HID);
  float2* xch = (float2*)(sm + OFF_XCH) + grp * (4*GB*32);
  float4* rbq = (float4*)(sm + OFF_RBQ) + grp * (GB*3*WIDTH);
  float*  rbf = (float*)rbq;
  const float4* wbase = (const float4*)(sm + OFF_W) + q*(KQTOT*2*32) + lane;

  const float bj0 = sm[OFF_BIAS + 64*q + lane];
  const float bj1 = sm[OFF_BIAS + 64*q + lane + 32];

  // warp owns batches 4q..4q+3 for the cell update
  float cx0[4], cx1[4];
#pragma unroll
  for (int bb = 0; bb < 4; bb++){ cx0[bb] = 0.f; cx1[bb] = 0.f; }

  float wl0[3], wl1[3], blv[3];
#pragma unroll
  for (int ch = 0; ch < 3; ch++){
    wl0[ch] = sm[OFF_WL + ch*HID + lane];
    wl1[ch] = sm[OFF_WL + ch*HID + lane + 32];
    blv[ch] = sm[OFF_BL + ch];
  }

  for (int r = L0R; r < R0R; r++){
    // row buffer init from x (4-replicated quads)
    for (int i = q*32 + lane; i < GB*3*WIDTH; i += 128){
      int b = i / (3*WIDTH);
      int rem = i - b*(3*WIDTH);
      int ch = rem / WIDTH;
      int base = rem - ch*WIDTH;
      const float* xr = x + (size_t)(bgrp + b)*(3*WIDTH*WIDTH)
                          + ch*(WIDTH*WIDTH) + r*WIDTH;
      float v0 = xr[base];
      float v1 = (base+1 < WIDTH) ? xr[base+1] : 0.f;
      float v2 = (base+2 < WIDTH) ? xr[base+2] : 0.f;
      float v3 = (base+3 < WIDTH) ? xr[base+3] : 0.f;
      rbq[i] = make_float4(v0, v1, v2, v3);
    }
    GBAR();

    for (int c = RS; c < WIDTH; c++){
      // acc0/1[b]: u64 = (even-k partial, odd-k partial) for gates 64q+lane(+32)
      u64 acc0[GB], acc1[GB];
#pragma unroll
      for (int b = 0; b < GB; b++){
        acc0[b] = pack2(bj0, 0.f);
        acc1[b] = pack2(bj1, 0.f);
      }

      // ---- input k-quads ----
#pragma unroll
      for (int kq = 0; kq < KQ_IN; kq++){
        F4U w0, w1;
        w0.f4 = wbase[(kq*2 + 0)*32];
        w1.f4 = wbase[(kq*2 + 1)*32];
        int ch = kq >> 1, qi = kq & 1;
        int base = c - RS + 4*qi;
#pragma unroll
        for (int b = 0; b < GB; b++){
          F4U a; a.f4 = rbq[(b*3 + ch)*WIDTH + base];
          acc0[b] = ffma2(a.u.lo, w0.u.lo, acc0[b]);
          acc1[b] = ffma2(a.u.lo, w0.u.hi, acc1[b]);
          acc0[b] = ffma2(a.u.hi, w1.u.lo, acc0[b]);
          acc1[b] = ffma2(a.u.hi, w1.u.hi, acc1[b]);
        }
      }

      // ---- hidden k-quads ----
#pragma unroll 2
      for (int kq = 0; kq < KQ_HID; kq++){
        F4U w0, w1;
        w0.f4 = wbase[((KQ_IN + kq)*2 + 0)*32];
        w1.f4 = wbase[((KQ_IN + kq)*2 + 1)*32];
#pragma unroll
        for (int b = 0; b < GB; b++){
          F4U a; a.f4 = *(const float4*)&hxs[b*HID + 4*kq];
          acc0[b] = ffma2(a.u.lo, w0.u.lo, acc0[b]);
          acc1[b] = ffma2(a.u.lo, w0.u.hi, acc1[b]);
          acc0[b] = ffma2(a.u.hi, w1.u.lo, acc0[b]);
          acc1[b] = ffma2(a.u.hi, w1.u.hi, acc1[b]);
        }
      }

      // ---- finalize + export: gate type q for all 16 batches ----
#pragma unroll
      for (int b = 0; b < GB; b++){
        float e0, o0, e1, o1;
        unpack2(acc0[b], e0, o0);
        unpack2(acc1[b], e1, o1);
        xch[(q*GB + b)*32 + lane] = make_float2(e0 + o0, e1 + o1);
      }
      GBAR();

      // ---- cell update for owned batches 4q..4q+3 ----
      float p[4][3];
#pragma unroll
      for (int bb = 0; bb < 4; bb++){
        int b = 4*q + bb;
        float2 gi = xch[(0*GB + b)*32 + lane];
        float2 gf = xch[(1*GB + b)*32 + lane];
        float2 gg = xch[(2*GB + b)*32 + lane];
        float2 go = xch[(3*GB + b)*32 + lane];
        float c0 = sigf(gf.x)*cx0[bb] + sigf(gi.x)*tanha(gg.x);
        float c1 = sigf(gf.y)*cx1[bb] + sigf(gi.y)*tanha(gg.y);
        cx0[bb] = c0; cx1[bb] = c1;
        float h0 = sigf(go.x)*tanha(c0);
        float h1 = sigf(go.y)*tanha(c1);
        hxs[b*HID + lane]      = h0;
        hxs[b*HID + lane + 32] = h1;
#pragma unroll
        for (int ch = 0; ch < 3; ch++)
          p[bb][ch] = h0*wl0[ch] + h1*wl1[ch];
      }

      // butterfly-reduce the 12 head dot-products
#pragma unroll
      for (int off = 16; off >= 1; off >>= 1)
#pragma unroll
        for (int bb = 0; bb < 4; bb++)
#pragma unroll
          for (int ch = 0; ch < 3; ch++)
            p[bb][ch] += __shfl_xor_sync(FULLMASK, p[bb][ch], off);

      // leaky-relu, write v into replicated row-buffer quads + output
#pragma unroll
      for (int bb = 0; bb < 4; bb++)
#pragma unroll
        for (int ch = 0; ch < 3; ch++){
          if (lane == bb*3 + ch){
            float v = p[bb][ch] + blv[ch];
            v = fmaxf(v, 0.01f*v);
            int b = 4*q + bb;
#pragma unroll
            for (int t = 0; t < 4; t++)
              rbf[((b*3 + ch)*WIDTH + (c - t))*4 + t] = v;
            out[((size_t)(bgrp + b)*3 + ch)*(OW*OW)
                + (r - L0R)*OW + (c - RS)] = v;
          }
        }
      GBAR();
    }
  }
}

extern "C" void kernel_launch(void* const* d_in, const int* in_sizes, int n_in,
                              void* d_out, int out_size)
{
  const float* x    = (const float*)d_in[0];
  const float* W_ih = (const float*)d_in[1];
  const float* W_hh = (const float*)d_in[2];
  const float* b_ih = (const float*)d_in[3];
  const float* b_hh = (const float*)d_in[4];
  const float* Wl   = (const float*)d_in[5];
  const float* bl   = (const float*)d_in[6];

  int B = in_sizes[0] / (3*WIDTH*WIDTH);
  int grid = B / CTAB;   // 4096/32 = 128 CTAs

  size_t smem = SMEM_FLOATS * sizeof(float);   // ~166 KB
  cudaFuncSetAttribute(pixelrnn_kernel,
                       cudaFuncAttributeMaxDynamicSharedMemorySize, (int)smem);

  pixelrnn_kernel<<<grid, NTHR, smem>>>(x, W_ih, W_hh, b_ih, b_hh, Wl, bl,
                                        (float*)d_out);
}

// round 7
// speedup vs baseline: 1.3615x; 1.3615x over previous
#include <cuda_runtime.h>

#define HID   64
#define G4    256
#define RS    8
#define KIH   24
#define WIDTH 24
#define L0R   8
#define R0R   24
#define OW    16
#define WB    8          // batches per warp-pair
#define NPAIR 4
#define NTHR  256
#define CTAB  32
#define KP    44         // k-pairs (88 k total)
#define RBW   25         // padded row width (float4 units)

// smem float offsets
#define OFF_W    0
#define W_FLOATS (2*KP*HID*4)                // 22528
#define OFF_BIAS (OFF_W + W_FLOATS)          // 22528
#define OFF_WL   (OFF_BIAS + G4)             // 22784 (3*16 float4)
#define OFF_BL   (OFF_WL + 192)              // 22976
#define OFF_HX   (OFF_BL + 4)                // 22980 (byte 91920, 16B aligned)
#define HXBUF    (NPAIR*WB*HID)              // 2048 per buffer
#define OFF_RBQ  (OFF_HX + 2*HXBUF)          // 27076 (byte 108304, 16B aligned)
#define RBQ_FLOATS (NPAIR*WB*3*RBW*4)        // 9600
#define SMEM_FLOATS (OFF_RBQ + RBQ_FLOATS)   // 36676 -> ~147 KB

typedef unsigned long long u64;

union F4U { float4 f4; struct { u64 lo, hi; } u; };

static __device__ __forceinline__ u64 pack2(float a, float b){
  u64 r; asm("mov.b64 %0, {%1, %2};" : "=l"(r) : "f"(a), "f"(b)); return r;
}
static __device__ __forceinline__ void unpack2(u64 v, float& a, float& b){
  asm("mov.b64 {%0, %1}, %2;" : "=f"(a), "=f"(b) : "l"(v));
}
static __device__ __forceinline__ u64 ffma2(u64 a, u64 b, u64 c){
  u64 d; asm("fma.rn.f32x2 %0, %1, %2, %3;" : "=l"(d) : "l"(a), "l"(b), "l"(c));
  return d;
}
static __device__ __forceinline__ float tanha(float x){
  float y; asm("tanh.approx.f32 %0, %1;" : "=f"(y) : "f"(x)); return y;
}
static __device__ __forceinline__ float sigf(float x){
  return fmaf(tanha(0.5f*x), 0.5f, 0.5f);
}

#define PBAR() asm volatile("bar.sync %0, 64;" :: "r"(pair + 1) : "memory")

__global__ void __launch_bounds__(NTHR, 1)
pixelrnn_kernel(const float* __restrict__ x,
                const float* __restrict__ W_ih,
                const float* __restrict__ W_hh,
                const float* __restrict__ b_ih,
                const float* __restrict__ b_hh,
                const float* __restrict__ Wl,
                const float* __restrict__ bl,
                float* __restrict__ out)
{
  extern __shared__ float sm[];
  const int tid  = threadIdx.x;
  const int warp = tid >> 5, lane = tid & 31;
  const int pair = warp >> 1, half = warp & 1;
  const int h    = 32*half + lane;     // owned hidden unit

  // ---- stage weights ----
  // float4 W4[j*KP*64 + kp*64 + hh] = ( w(k,rA), w(k+1,rA), w(k,rB), w(k+1,rB) )
  //   j=0: rA=hh (i-gate), rB=64+hh (f);  j=1: rA=128+hh (g), rB=192+hh (o)
  //   k = 2*kp; k<24 -> W_ih col k; k>=24 -> W_hh col k-24
  {
    float4* W4 = (float4*)(sm + OFF_W);
    for (int i = tid; i < 2*KP*HID; i += NTHR){
      int j  = i / (KP*HID);
      int rem = i - j*(KP*HID);
      int kp = rem >> 6, hh = rem & 63;
      int k  = 2*kp;
      int r0 = j*128 + hh, r1 = r0 + 64;
      float4 v;
      if (k < KIH){
        v = make_float4(W_ih[r0*KIH + k], W_ih[r0*KIH + k + 1],
                        W_ih[r1*KIH + k], W_ih[r1*KIH + k + 1]);
      } else {
        int kk = k - KIH;
        v = make_float4(W_hh[r0*HID + kk], W_hh[r0*HID + kk + 1],
                        W_hh[r1*HID + kk], W_hh[r1*HID + kk + 1]);
      }
      W4[i] = v;
    }
  }
  for (int i = tid; i < G4; i += NTHR) sm[OFF_BIAS + i] = b_ih[i] + b_hh[i];
  for (int i = tid; i < 3*HID; i += NTHR) sm[OFF_WL + i] = Wl[i];
  if (tid < 3) sm[OFF_BL + tid] = bl[tid];
  for (int i = tid; i < 2*HXBUF; i += NTHR) sm[OFF_HX + i] = 0.f;
  __syncthreads();

  const int bpair = blockIdx.x * CTAB + pair * WB;
  float* hxb0 = sm + OFF_HX + pair * (WB*HID);            // buffer 0
  float* hxb1 = hxb0 + HXBUF;                             // buffer 1
  float4* rbq = (float4*)(sm + OFF_RBQ) + pair * (WB*3*RBW);
  float*  rbf = (float*)rbq;
  const float4* wp  = (const float4*)(sm + OFF_W) + h;    // +kp*64 ; plane1 +KP*64
  const float4* wlq = (const float4*)(sm + OFF_WL);

  // biases for owned gates
  u64 bj[4];
  bj[0] = pack2(sm[OFF_BIAS + h],       0.f);   // i
  bj[1] = pack2(sm[OFF_BIAS + 64 + h],  0.f);   // f
  bj[2] = pack2(sm[OFF_BIAS + 128 + h], 0.f);   // g
  bj[3] = pack2(sm[OFF_BIAS + 192 + h], 0.f);   // o

  float cx[WB];
#pragma unroll
  for (int b = 0; b < WB; b++) cx[b] = 0.f;

  const int  vb  = lane / 3, vch = lane - 3*vb;   // v-lane mapping (lane<24)
  const bool vact = (lane < 24);
  const float blv = vact ? sm[OFF_BL + vch] : 0.f;
  float* outp = vact ? out + ((size_t)(bpair + vb)*3 + vch)*(OW*OW) : out;

  int ph = 0;   // hx read-buffer parity (continuous across rows)
  int sctr = 0; // output step counter

  for (int r = L0R; r < R0R; r++){
    // row buffer init from x: quads base 0..19 (cols 0..22; col 23 never fed)
    for (int i = 32*half + lane; i < WB*3*20; i += 64){
      int b = i / 60;
      int rem = i - b*60;
      int ch = rem / 20;
      int base = rem - ch*20;
      const float* xr = x + (size_t)(bpair + b)*(3*WIDTH*WIDTH)
                          + ch*(WIDTH*WIDTH) + r*WIDTH + base;
      rbq[(b*3 + ch)*RBW + base] = make_float4(xr[0], xr[1], xr[2], xr[3]);
    }
    PBAR();

    for (int c = RS; c < WIDTH; c++){
      const float* hxr = ph ? hxb1 : hxb0;   // read h(t-1)
      float* hxw = ph ? hxb0 : hxb1;         // write h(t)
      const float4* hxq = (const float4*)hxr;

      // acc[b][g]: u64 = (even-k, odd-k) partials for gate-type g of hid h
      u64 acc[WB][4];
#pragma unroll
      for (int b = 0; b < WB; b++)
#pragma unroll
        for (int g = 0; g < 4; g++) acc[b][g] = bj[g];

      // ---- input feed: 6 quads ----
#pragma unroll
      for (int kq = 0; kq < 6; kq++){
        F4U w0, w1, w2, w3;
        w0.f4 = wp[(2*kq + 0)*64];
        w1.f4 = wp[(2*kq + 1)*64];
        w2.f4 = wp[KP*64 + (2*kq + 0)*64];
        w3.f4 = wp[KP*64 + (2*kq + 1)*64];
        int ch = kq >> 1;
        int base = c - RS + 4*(kq & 1);
#pragma unroll
        for (int b = 0; b < WB; b++){
          F4U a; a.f4 = rbq[(b*3 + ch)*RBW + base];
          acc[b][0] = ffma2(a.u.lo, w0.u.lo, acc[b][0]);
          acc[b][1] = ffma2(a.u.lo, w0.u.hi, acc[b][1]);
          acc[b][2] = ffma2(a.u.lo, w2.u.lo, acc[b][2]);
          acc[b][3] = ffma2(a.u.lo, w2.u.hi, acc[b][3]);
          acc[b][0] = ffma2(a.u.hi, w1.u.lo, acc[b][0]);
          acc[b][1] = ffma2(a.u.hi, w1.u.hi, acc[b][1]);
          acc[b][2] = ffma2(a.u.hi, w3.u.lo, acc[b][2]);
          acc[b][3] = ffma2(a.u.hi, w3.u.hi, acc[b][3]);
        }
      }

      // ---- hidden feed: 16 quads ----
#pragma unroll
      for (int kq = 0; kq < 16; kq++){
        F4U w0, w1, w2, w3;
        w0.f4 = wp[(12 + 2*kq + 0)*64];
        w1.f4 = wp[(12 + 2*kq + 1)*64];
        w2.f4 = wp[KP*64 + (12 + 2*kq + 0)*64];
        w3.f4 = wp[KP*64 + (12 + 2*kq + 1)*64];
#pragma unroll
        for (int b = 0; b < WB; b++){
          F4U a; a.f4 = hxq[b*16 + kq];
          acc[b][0] = ffma2(a.u.lo, w0.u.lo, acc[b][0]);
          acc[b][1] = ffma2(a.u.lo, w0.u.hi, acc[b][1]);
          acc[b][2] = ffma2(a.u.lo, w2.u.lo, acc[b][2]);
          acc[b][3] = ffma2(a.u.lo, w2.u.hi, acc[b][3]);
          acc[b][0] = ffma2(a.u.hi, w1.u.lo, acc[b][0]);
          acc[b][1] = ffma2(a.u.hi, w1.u.hi, acc[b][1]);
          acc[b][2] = ffma2(a.u.hi, w3.u.lo, acc[b][2]);
          acc[b][3] = ffma2(a.u.hi, w3.u.hi, acc[b][3]);
        }
      }

      // ---- lane-local cell update (no exchange) ----
#pragma unroll
      for (int b = 0; b < WB; b++){
        float e, o, gi, gf, gg, go;
        unpack2(acc[b][0], e, o); gi = e + o;
        unpack2(acc[b][1], e, o); gf = e + o;
        unpack2(acc[b][2], e, o); gg = e + o;
        unpack2(acc[b][3], e, o); go = e + o;
        float cn = sigf(gf)*cx[b] + sigf(gi)*tanha(gg);
        cx[b] = cn;
        hxw[b*HID + h] = sigf(go)*tanha(cn);
      }
      PBAR();   // single barrier: partner hx now visible

      // ---- head v: duplicate-computed by both warps from smem hx ----
      if (vact){
        const float4* hq = (const float4*)hxw;
        u64 va = pack2(0.f, 0.f);
#pragma unroll
        for (int j = 0; j < 16; j++){
          F4U a; a.f4 = hq[vb*16 + j];
          F4U w; w.f4 = wlq[vch*16 + j];
          va = ffma2(a.u.lo, w.u.lo, va);
          va = ffma2(a.u.hi, w.u.hi, va);
        }
        float v0, v1; unpack2(va, v0, v1);
        float v = v0 + v1 + blv;
        v = fmaxf(v, 0.01f*v);
        // write all 4 replicas ourselves -> own reads need no extra barrier
#pragma unroll
        for (int t = 0; t < 4; t++)
          rbf[((vb*3 + vch)*RBW + (c - t))*4 + t] = v;
        if (half == 0) outp[sctr] = v;
      }
      ph ^= 1;
      sctr++;
    }
  }
}

extern "C" void kernel_launch(void* const* d_in, const int* in_sizes, int n_in,
                              void* d_out, int out_size)
{
  const float* x    = (const float*)d_in[0];
  const float* W_ih = (const float*)d_in[1];
  const float* W_hh = (const float*)d_in[2];
  const float* b_ih = (const float*)d_in[3];
  const float* b_hh = (const float*)d_in[4];
  const float* Wl   = (const float*)d_in[5];
  const float* bl   = (const float*)d_in[6];

  int B = in_sizes[0] / (3*WIDTH*WIDTH);
  int grid = B / CTAB;   // 4096/32 = 128 CTAs

  size_t smem = SMEM_FLOATS * sizeof(float);   // ~147 KB
  cudaFuncSetAttribute(pixelrnn_kernel,
                       cudaFuncAttributeMaxDynamicSharedMemorySize, (int)smem);

  pixelrnn_kernel<<<grid, NTHR, smem>>>(x, W_ih, W_hh, b_ih, b_hh, Wl, bl,
                                        (float*)d_out);
}